// round 7
// baseline (speedup 1.0000x reference)
#include <cuda_runtime.h>
#include <cuda_bf16.h>
#include <cstdint>

// ============================================================================
// Problem dims
// ============================================================================
#define D_DIM   4096
#define M_ROWS  32768            // 8 * 4096

// GEMM tiling: CTA 128x128. Tensor warps (0-3): n 0..95 bf16 HMMA.
// dp4a warps (4-7): n 96..127 int8 on ALU pipe. One of each per SMSP.
#define TILE_M   128
#define TILE_N   128
#define TILE_K   64
#define KCHUNKS  (D_DIM / TILE_K)   // 64
#define NSTAGE   4

// Tiled global layouts: per (panel, kchunk) block
#define BLK16_SZ  16384          // 128 rows x 128 B (bf16)
#define BLK8_SZ   8192           // 128 rows x 64 B  (int8)

// SMEM stage layout
#define A16_OFF   0
#define B16_OFF   16384          // 96 rows x 128B used by tensor warps
#define A8_OFF    28672          // 128 rows x 64B
#define B8_OFF    36864          // 32 rows (96..127) x 64B
#define STAGE_SZ  38912
#define BAR_OFF   (NSTAGE * STAGE_SZ)
#define SMEM_BYTES (BAR_OFF + 128)

// ============================================================================
// Scratch (device globals; no allocation anywhere)
// ============================================================================
__device__ __align__(256) __nv_bfloat16 g_q [(size_t)M_ROWS * D_DIM];  // 256 MB
__device__ __align__(256) __nv_bfloat16 g_w [(size_t)D_DIM * D_DIM];   // 32 MB
__device__ __align__(256) int8_t        g_q8[(size_t)M_ROWS * D_DIM];  // 128 MB
__device__ __align__(256) int8_t        g_w8[(size_t)D_DIM * D_DIM];   // 16 MB
__device__ float  g_rs[M_ROWS];   // 1 / x_scale^2 per row
__device__ double g_ksum;

// ============================================================================
// Helpers
// ============================================================================
__device__ __forceinline__ uint32_t smem_to_u32(const void* smem_ptr) {
    uint32_t addr;
    asm("{ .reg .u64 tmp; cvta.to.shared.u64 tmp, %1; cvt.u32.u64 %0, tmp; }"
        : "=r"(addr) : "l"(smem_ptr));
    return addr;
}

// bf16 tile swizzle: (row 0..127, 16B unit 0..7) -> byte offset (verified R4-6)
__device__ __forceinline__ uint32_t sw_off(int row, int u) {
    return (uint32_t)(row * 128 + ((u ^ (row & 7)) << 4));
}
// int8 tile swizzle: (row 0..127, 16B unit 0..3) -> byte offset (verified R2)
__device__ __forceinline__ uint32_t sw8(int row, int u) {
    return (uint32_t)(row * 64 + ((u ^ ((row >> 1) & 3)) << 4));
}

__device__ __forceinline__ void cp_bulk(uint32_t smem_dst, const void* gsrc,
                                        uint32_t bytes, uint32_t mbar) {
    asm volatile(
        "cp.async.bulk.shared::cluster.global.mbarrier::complete_tx::bytes "
        "[%0], [%1], %2, [%3];"
        :: "r"(smem_dst), "l"(__cvta_generic_to_global(gsrc)), "r"(bytes), "r"(mbar)
        : "memory");
}

#define MBARRIER_INIT(addr, count) \
    asm volatile("mbarrier.init.shared.b64 [%0], %1;" \
                 :: "r"((uint32_t)(addr)), "r"((uint32_t)(count)) : "memory")

#define MBARRIER_ARRIVE(addr) \
    asm volatile("mbarrier.arrive.shared.b64 _, [%0];" \
                 :: "r"((uint32_t)(addr)) : "memory")

#define MBARRIER_ARRIVE_EXPECT_TX(addr, bytes) \
    asm volatile("mbarrier.arrive.expect_tx.shared.b64 _, [%0], %1;" \
                 :: "r"((uint32_t)(addr)), "r"((uint32_t)(bytes)) : "memory")

#define MBARRIER_WAIT_PARITY(mbar_smem_addr, phase_parity) do { \
    uint32_t _mbar = (uint32_t)(mbar_smem_addr); \
    uint32_t _parity = (uint32_t)(phase_parity); \
    uint32_t _done; \
    asm volatile( \
        "{\n\t" \
        ".reg .pred p;\n\t" \
        "mbarrier.try_wait.parity.acquire.cta.shared::cta.b64 p, [%1], %2;\n\t" \
        "selp.b32 %0, 1, 0, p;\n\t" \
        "}" \
        : "=r"(_done) : "r"(_mbar), "r"(_parity) : "memory"); \
    if (!_done) { \
        asm volatile( \
            "{\n\t" \
            ".reg .pred P1;\n\t" \
            "WAIT_LOOP_%=:\n\t" \
            "mbarrier.try_wait.parity.acquire.cta.shared::cta.b64 P1, [%0], %1, 0x989680;\n\t" \
            "@P1 bra.uni WAIT_DONE_%=;\n\t" \
            "bra.uni WAIT_LOOP_%=;\n\t" \
            "WAIT_DONE_%=:\n\t" \
            "}" \
            :: "r"(_mbar), "r"(_parity) : "memory"); \
    } \
} while(0)

__device__ __forceinline__ void ldm_x4(uint32_t* r, uint32_t addr) {
    asm volatile("ldmatrix.sync.aligned.m8n8.x4.shared.b16 {%0,%1,%2,%3}, [%4];"
                 : "=r"(r[0]), "=r"(r[1]), "=r"(r[2]), "=r"(r[3]) : "r"(addr));
}

__device__ __forceinline__ void mma_bf16(float* c, const uint32_t* a,
                                         uint32_t b0, uint32_t b1) {
    asm volatile(
        "mma.sync.aligned.m16n8k16.row.col.f32.bf16.bf16.f32 "
        "{%0,%1,%2,%3}, {%4,%5,%6,%7}, {%8,%9}, {%0,%1,%2,%3};"
        : "+f"(c[0]), "+f"(c[1]), "+f"(c[2]), "+f"(c[3])
        : "r"(a[0]), "r"(a[1]), "r"(a[2]), "r"(a[3]), "r"(b0), "r"(b1));
}

// ============================================================================
// Kernel 0/1: kernel-matrix mean (double accumulate)
// ============================================================================
__global__ void zero_kernel() { g_ksum = 0.0; }

__global__ void ksum_kernel(const float* __restrict__ k) {
    float s = 0.f;
    const float4* k4 = (const float4*)k;
    const int n4 = (D_DIM * D_DIM) / 4;
    for (int i = blockIdx.x * blockDim.x + threadIdx.x; i < n4; i += gridDim.x * blockDim.x) {
        float4 v = k4[i];
        s += v.x + v.y + v.z + v.w;
    }
#pragma unroll
    for (int o = 16; o > 0; o >>= 1) s += __shfl_xor_sync(0xffffffffu, s, o);
    __shared__ float sb[8];
    int wid = threadIdx.x >> 5, lid = threadIdx.x & 31;
    if (lid == 0) sb[wid] = s;
    __syncthreads();
    if (threadIdx.x == 0) {
        float t = 0.f;
        for (int i = 0; i < 8; i++) t += sb[i];
        atomicAdd(&g_ksum, (double)t);
    }
}

// ============================================================================
// Kernel 2: sign(kernel - mean), transposed to [f][d], bf16 + int8 tiled
// ============================================================================
__global__ void sign_kernel(const float* __restrict__ k) {
    __shared__ float t[32][33];
    float mean = (float)(g_ksum * (1.0 / 16777216.0));
    int d = blockIdx.y * 32 + threadIdx.y;
    int f = blockIdx.x * 32 + threadIdx.x;
    t[threadIdx.y][threadIdx.x] = k[(size_t)d * D_DIM + f];
    __syncthreads();
    int f2 = blockIdx.x * 32 + threadIdx.y;     // output row (n)
    int d2 = blockIdx.y * 32 + threadIdx.x;     // output col (k)
    float v = t[threadIdx.x][threadIdx.y] - mean;
    float s = (v > 0.f) ? 1.f : ((v < 0.f) ? -1.f : 0.f);
    int p  = f2 >> 7, r = f2 & 127;
    int kc = d2 >> 6, w = d2 & 63;
    // bf16 tiled
    int u16 = w >> 3, e16 = w & 7;
    *(__nv_bfloat16*)((char*)g_w + ((size_t)p * KCHUNKS + kc) * BLK16_SZ
                      + sw_off(r, u16) + e16 * 2) = __float2bfloat16_rn(s);
    // int8 tiled
    int u8 = w >> 4, e8 = w & 15;
    *((char*)g_w8 + ((size_t)p * KCHUNKS + kc) * BLK8_SZ + sw8(r, u8) + e8) =
        (char)(int)s;
}

// ============================================================================
// Kernel 3: per-row RMSNorm + int8 fake-quant -> bf16 + int8 tiled, 1/sc^2
// Thread t owns k in [16t, 16t+16).
// ============================================================================
__global__ void quant_kernel(const float* __restrict__ x) {
    int row = blockIdx.x;
    int tid = threadIdx.x;
    const float4* xr = (const float4*)(x + (size_t)row * D_DIM);
    float4 v[4];
    float ss = 0.f, am = 0.f;
#pragma unroll
    for (int i = 0; i < 4; i++) {
        v[i] = xr[tid * 4 + i];
        ss += v[i].x * v[i].x + v[i].y * v[i].y + v[i].z * v[i].z + v[i].w * v[i].w;
        am = fmaxf(am, fmaxf(fmaxf(fabsf(v[i].x), fabsf(v[i].y)),
                             fmaxf(fabsf(v[i].z), fabsf(v[i].w))));
    }
#pragma unroll
    for (int o = 16; o > 0; o >>= 1) {
        ss += __shfl_xor_sync(0xffffffffu, ss, o);
        am = fmaxf(am, __shfl_xor_sync(0xffffffffu, am, o));
    }
    __shared__ float s_ss[8], s_am[8];
    __shared__ float sh_rinv, sh_sc;
    int wid = tid >> 5, lid = tid & 31;
    if (lid == 0) { s_ss[wid] = ss; s_am[wid] = am; }
    __syncthreads();
    if (tid == 0) {
        float t = 0.f, m = 0.f;
        for (int i = 0; i < 8; i++) { t += s_ss[i]; m = fmaxf(m, s_am[i]); }
        float rinv = rsqrtf(t * (1.f / 4096.f) + 1e-5f);
        float amax = m * rinv;
        float sc = 127.f / fmaxf(amax, 1e-5f);
        sh_rinv = rinv; sh_sc = sc;
        g_rs[row] = 1.f / (sc * sc);
    }
    __syncthreads();
    float rinv = sh_rinv, sc = sh_sc;
    unsigned pk[8], pk8[4];
#pragma unroll
    for (int i = 0; i < 4; i++) {
        float a[4] = { v[i].x, v[i].y, v[i].z, v[i].w };
        unsigned short h[4];
        unsigned b8 = 0;
#pragma unroll
        for (int j = 0; j < 4; j++) {
            float xn = a[j] * rinv;
            float r = rintf(xn * sc);                // round half-to-even == jnp.round
            r = fminf(fmaxf(r, -128.f), 127.f);
            h[j] = __bfloat16_as_ushort(__float2bfloat16_rn(r));   // exact
            b8 |= ((unsigned)((int)r & 0xff)) << (j * 8);
        }
        pk[i * 2]     = (unsigned)h[0] | ((unsigned)h[1] << 16);
        pk[i * 2 + 1] = (unsigned)h[2] | ((unsigned)h[3] << 16);
        pk8[i] = b8;
    }
    int p = row >> 7, r = row & 127;
    int kc = tid >> 2;
    // bf16 tiled: two 16B units
    int u0 = (tid & 3) * 2;
    char* base16 = (char*)g_q + ((size_t)p * KCHUNKS + kc) * BLK16_SZ;
    *(uint4*)(base16 + sw_off(r, u0))     = make_uint4(pk[0], pk[1], pk[2], pk[3]);
    *(uint4*)(base16 + sw_off(r, u0 + 1)) = make_uint4(pk[4], pk[5], pk[6], pk[7]);
    // int8 tiled: one 16B unit
    char* base8 = (char*)g_q8 + ((size_t)p * KCHUNKS + kc) * BLK8_SZ;
    *(uint4*)(base8 + sw8(r, tid & 3)) = make_uint4(pk8[0], pk8[1], pk8[2], pk8[3]);
}

// ============================================================================
// Kernel 4: hybrid GEMM. Warps 0-3: bf16 HMMA 128x96 (warp 64x48).
// Warps 4-7: int8 dp4a 128x32 (warp 32x32), n 96..127. One each per SMSP.
// 4-stage bulk-copy ring, full/empty mbarriers, no mainloop syncthreads.
// ============================================================================
__global__ void __launch_bounds__(256, 1) gemm_kernel(float* __restrict__ out) {
    extern __shared__ char smem[];
    const uint32_t sbase = smem_to_u32(smem);
    const uint32_t fbar  = sbase + BAR_OFF;
    const uint32_t ebar  = sbase + BAR_OFF + 64;
    const int tid = threadIdx.x;
    const int wid = tid >> 5, lane = tid & 31;
    const int m0 = blockIdx.y * TILE_M;
    const int n0 = blockIdx.x * TILE_N;

    const char* gA16 = (const char*)g_q  + (size_t)blockIdx.y * KCHUNKS * BLK16_SZ;
    const char* gB16 = (const char*)g_w  + (size_t)blockIdx.x * KCHUNKS * BLK16_SZ;
    const char* gA8  = (const char*)g_q8 + (size_t)blockIdx.y * KCHUNKS * BLK8_SZ;
    const char* gB8  = (const char*)g_w8 + (size_t)blockIdx.x * KCHUNKS * BLK8_SZ;

    if (tid == 0) {
#pragma unroll
        for (int s = 0; s < NSTAGE; s++) {
            MBARRIER_INIT(fbar + s * 8, 1);
            MBARRIER_INIT(ebar + s * 8, 8);
        }
    }
    __syncthreads();

    auto issue = [&](int kc, int s) {
        uint32_t mb = fbar + s * 8;
        MBARRIER_ARRIVE_EXPECT_TX(mb, STAGE_SZ);
        uint32_t dst = sbase + s * STAGE_SZ;
        cp_bulk(dst + A16_OFF, gA16 + (size_t)kc * BLK16_SZ,        16384, mb);
        cp_bulk(dst + B16_OFF, gB16 + (size_t)kc * BLK16_SZ,        12288, mb);
        cp_bulk(dst + A8_OFF,  gA8  + (size_t)kc * BLK8_SZ,          8192, mb);
        cp_bulk(dst + B8_OFF,  gB8  + (size_t)kc * BLK8_SZ + 6144,   2048, mb);
    };

    if (tid == 0) {
#pragma unroll
        for (int s = 0; s < NSTAGE; s++) issue(s, s);
    }

    if (wid < 4) {
        // ----------------- tensor warps: 64x48, n 0..95 -----------------
        const int warp_m = wid >> 1;      // 0..1
        const int warp_n = wid & 1;       // 0..1
        float acc[4][6][4];
#pragma unroll
        for (int i = 0; i < 4; i++)
#pragma unroll
            for (int j = 0; j < 6; j++)
#pragma unroll
                for (int c = 0; c < 4; c++) acc[i][j][c] = 0.f;

        const int lr = (lane & 7) + ((lane >> 3) & 1) * 8;
        const int lk = lane >> 4;

        for (int kc = 0; kc < KCHUNKS; kc++) {
            const int s = kc & (NSTAGE - 1);
            const int ph = (kc / NSTAGE) & 1;
            MBARRIER_WAIT_PARITY(fbar + s * 8, ph);
            const uint32_t sa = sbase + s * STAGE_SZ + A16_OFF;
            const uint32_t sb = sbase + s * STAGE_SZ + B16_OFF;
#pragma unroll
            for (int ks = 0; ks < 4; ks++) {
                const int ku = 2 * ks + lk;
                uint32_t afr[4][4];
#pragma unroll
                for (int mf = 0; mf < 4; mf++)
                    ldm_x4(afr[mf], sa + sw_off(warp_m * 64 + mf * 16 + lr, ku));
                uint32_t bfr[3][4];
#pragma unroll
                for (int h = 0; h < 3; h++)
                    ldm_x4(bfr[h], sb + sw_off(warp_n * 48 + h * 16 + lr, ku));
#pragma unroll
                for (int mf = 0; mf < 4; mf++) {
#pragma unroll
                    for (int nf = 0; nf < 6; nf++) {
                        uint32_t b0 = bfr[nf >> 1][nf & 1];
                        uint32_t b1 = bfr[nf >> 1][(nf & 1) + 2];
                        mma_bf16(acc[mf][nf], afr[mf], b0, b1);
                    }
                }
            }
            if (lane == 0) MBARRIER_ARRIVE(ebar + s * 8);
            if (tid == 0 && kc + NSTAGE < KCHUNKS) {
                MBARRIER_WAIT_PARITY(ebar + s * 8, ph);
                issue(kc + NSTAGE, s);
            }
        }

        const int group = lane >> 2, tig = lane & 3;
#pragma unroll
        for (int mf = 0; mf < 4; mf++) {
            int r0 = m0 + warp_m * 64 + mf * 16 + group;
            float rs0 = g_rs[r0];
            float rs1 = g_rs[r0 + 8];
            float* o0 = out + (size_t)r0 * D_DIM;
            float* o1 = out + (size_t)(r0 + 8) * D_DIM;
#pragma unroll
            for (int nf = 0; nf < 6; nf++) {
                int col = n0 + warp_n * 48 + nf * 8 + tig * 2;
                float2 v0, v1;
                v0.x = acc[mf][nf][0] * rs0;
                v0.y = acc[mf][nf][1] * rs0;
                v1.x = acc[mf][nf][2] * rs1;
                v1.y = acc[mf][nf][3] * rs1;
                *(float2*)(o0 + col) = v0;
                *(float2*)(o1 + col) = v1;
            }
        }
    } else {
        // ----------------- dp4a warps: 32x32, n 96..127 -----------------
        const int d  = wid - 4;           // 0..3: m rows d*32 .. d*32+31
        const int mi = lane >> 3;         // 0..3: rows mi + 4j (j 0..7)
        const int nb = (lane & 7) * 4;    // local n-row base 0..28 (cols 96+nb..)
        int acc8[8][4];
#pragma unroll
        for (int j = 0; j < 8; j++)
#pragma unroll
            for (int jj = 0; jj < 4; jj++) acc8[j][jj] = 0;

        for (int kc = 0; kc < KCHUNKS; kc++) {
            const int s = kc & (NSTAGE - 1);
            const int ph = (kc / NSTAGE) & 1;
            MBARRIER_WAIT_PARITY(fbar + s * 8, ph);
            const char* a8 = smem + s * STAGE_SZ + A8_OFF;
            const char* b8 = smem + s * STAGE_SZ + B8_OFF;
#pragma unroll
            for (int u = 0; u < 4; u++) {
                uint4 ar[8], br[4];
#pragma unroll
                for (int j = 0; j < 8; j++)
                    ar[j] = *(const uint4*)(a8 + sw8(d * 32 + mi + 4 * j, u));
#pragma unroll
                for (int jj = 0; jj < 4; jj++)
                    br[jj] = *(const uint4*)(b8 + sw8(nb + jj, u));
#pragma unroll
                for (int j = 0; j < 8; j++) {
#pragma unroll
                    for (int jj = 0; jj < 4; jj++) {
                        int sacc = acc8[j][jj];
                        sacc = __dp4a((int)ar[j].x, (int)br[jj].x, sacc);
                        sacc = __dp4a((int)ar[j].y, (int)br[jj].y, sacc);
                        sacc = __dp4a((int)ar[j].z, (int)br[jj].z, sacc);
                        sacc = __dp4a((int)ar[j].w, (int)br[jj].w, sacc);
                        acc8[j][jj] = sacc;
                    }
                }
            }
            if (lane == 0) MBARRIER_ARRIVE(ebar + s * 8);
        }

#pragma unroll
        for (int j = 0; j < 8; j++) {
            int row = m0 + d * 32 + mi + 4 * j;
            float rs = g_rs[row];
            float4 o;
            o.x = (float)acc8[j][0] * rs;
            o.y = (float)acc8[j][1] * rs;
            o.z = (float)acc8[j][2] * rs;
            o.w = (float)acc8[j][3] * rs;
            *(float4*)(out + (size_t)row * D_DIM + n0 + 96 + nb) = o;
        }
    }
}

// ============================================================================
// kernel_launch
// ============================================================================
extern "C" void kernel_launch(void* const* d_in, const int* in_sizes, int n_in,
                              void* d_out, int out_size) {
    const float* x    = (const float*)d_in[0];
    const float* kern = (const float*)d_in[1];
    if (n_in >= 2 && in_sizes[0] < in_sizes[1]) {    // x is the bigger tensor
        x    = (const float*)d_in[1];
        kern = (const float*)d_in[0];
    }

    cudaFuncSetAttribute(gemm_kernel, cudaFuncAttributeMaxDynamicSharedMemorySize, SMEM_BYTES);

    zero_kernel<<<1, 1>>>();
    ksum_kernel<<<1024, 256>>>(kern);
    sign_kernel<<<dim3(D_DIM / 32, D_DIM / 32), dim3(32, 32)>>>(kern);
    quant_kernel<<<M_ROWS, 256>>>(x);
    // grid.x fastest: 32 n-tiles share one A panel; weights stay L2-hot
    gemm_kernel<<<dim3(D_DIM / TILE_N, M_ROWS / TILE_M), 256, SMEM_BYTES>>>((float*)d_out);
}